// round 1
// baseline (speedup 1.0000x reference)
#include <cuda_runtime.h>

#define SEQ   512
#define BATCH 1024
#define NTAG  64
#define NEGINF -10000.0f

// Edual[i*32 + l] = packed f32x2 ( exp(T[l][i]), exp(T[l+32][i]) )
__device__ __align__(16) unsigned long long g_Edual[NTAG * 32];

__device__ __forceinline__ float ex2f_(float x) {
    float y; asm("ex2.approx.ftz.f32 %0, %1;" : "=f"(y) : "f"(x)); return y;
}
__device__ __forceinline__ float lg2f_(float x) {
    float y; asm("lg2.approx.ftz.f32 %0, %1;" : "=f"(y) : "f"(x)); return y;
}
__device__ __forceinline__ unsigned long long fma2_(unsigned long long a,
                                                    unsigned long long b,
                                                    unsigned long long c) {
    unsigned long long d;
    asm("fma.rn.f32x2 %0, %1, %2, %3;" : "=l"(d) : "l"(a), "l"(b), "l"(c));
    return d;
}
__device__ __forceinline__ unsigned long long add2_(unsigned long long a,
                                                    unsigned long long b) {
    unsigned long long d;
    asm("add.rn.f32x2 %0, %1, %2;" : "=l"(d) : "l"(a), "l"(b));
    return d;
}
__device__ __forceinline__ unsigned long long dup_(float x) {
    unsigned long long r;
    asm("mov.b64 %0, {%1, %1};" : "=l"(r) : "f"(x));
    return r;
}
__device__ __forceinline__ void unpack_(unsigned long long v, float& x, float& y) {
    asm("mov.b64 {%0, %1}, %2;" : "=f"(x), "=f"(y) : "l"(v));
}

// Tiny setup: E = exp(transition), stored lane-major so the main kernel's
// per-lane register load of its two tag rows is fully coalesced.
__global__ void crf_setup(const float* __restrict__ trans) {
    int t = blockIdx.x * blockDim.x + threadIdx.x;
    if (t >= NTAG * 32) return;
    int i = t >> 5, l = t & 31;
    float e0 = __expf(trans[l * NTAG + i]);          // exp(-10000) -> 0 (START row)
    float e1 = __expf(trans[(l + 32) * NTAG + i]);
    unsigned long long u;
    asm("mov.b64 %0, {%1, %2};" : "=l"(u) : "f"(e0), "f"(e1));
    g_Edual[i * 32 + l] = u;
}

// One warp per batch. Lane l owns tags (l, l+32) packed in f32x2.
// E rows resident in 64 packed registers (128 fp32 values / lane).
__global__ void __launch_bounds__(256, 1)
crf_main(const float* __restrict__ feats,
         const float* __restrict__ mask,
         const float* __restrict__ trans,
         float* __restrict__ out) {
    const int lane = threadIdx.x & 31;
    const int w    = threadIdx.x >> 5;           // warp in block, 0..7
    const int b    = blockIdx.x * 8 + w;         // batch id, 0..1023

    // double-buffered duplicated-pair p values: pbuf[warp][phase][i] = (p_i, p_i)
    __shared__ __align__(16) unsigned long long pbuf[8][2][NTAG];

    unsigned long long E[NTAG];
#pragma unroll
    for (int i = 0; i < NTAG; ++i) E[i] = g_Edual[i * 32 + lane];

    // final-step additive row: transition[END_IDX=1][:]
    const float t_lo = trans[1 * NTAG + lane];
    const float t_hi = trans[1 * NTAG + 32 + lane];

    float a_lo = (lane == 0) ? 0.0f : NEGINF;    // START_IDX = 0
    float a_hi = NEGINF;

    const float* fbase = feats + (size_t)b * NTAG + lane;

    // prefetch depth 2 (DRAM latency ~600cyc > ~270cyc step time)
    float f_lo[2], f_hi[2], mk[2];
    f_lo[0] = fbase[0];
    f_hi[0] = fbase[32];
    f_lo[1] = fbase[(size_t)BATCH * NTAG];
    f_hi[1] = fbase[(size_t)BATCH * NTAG + 32];
    mk[0] = mask[b];
    mk[1] = mask[BATCH + b];

    const float L2E = 1.4426950408889634f;
    const float LN2 = 0.6931471805599453f;

#pragma unroll 1
    for (int s = 0; s < SEQ; s += 2) {
#pragma unroll
        for (int ph = 0; ph < 2; ++ph) {
            const int st = s + ph;
            const float fc_lo = f_lo[ph];
            const float fc_hi = f_hi[ph];
            const float mc    = mk[ph];

            // prefetch step st+2 (clamped; redundant tail load is harmless)
            int sp = st + 2;
            if (sp > SEQ - 1) sp = SEQ - 1;
            f_lo[ph] = fbase[(size_t)sp * BATCH * NTAG];
            f_hi[ph] = fbase[(size_t)sp * BATCH * NTAG + 32];
            mk[ph]   = mask[sp * BATCH + b];

            // exact warp max of alpha
            float m = fmaxf(a_lo, a_hi);
#pragma unroll
            for (int d = 16; d; d >>= 1)
                m = fmaxf(m, __shfl_xor_sync(0xffffffffu, m, d));

            const float c = -m * L2E;
            const float p_lo = ex2f_(fmaf(a_lo, L2E, c));
            const float p_hi = ex2f_(fmaf(a_hi, L2E, c));
            pbuf[w][ph][lane]      = dup_(p_lo);
            pbuf[w][ph][lane + 32] = dup_(p_hi);
            __syncwarp();

            // S_(l,l+32) = sum_i E[(l,l+32)][i] * p_i   (64 FFMA2, 32 LDS.128 bcast)
            const ulonglong2* pb =
                reinterpret_cast<const ulonglong2*>(&pbuf[w][ph][0]);
            unsigned long long acc0 = 0ull, acc1 = 0ull, acc2 = 0ull, acc3 = 0ull;
#pragma unroll
            for (int k = 0; k < 32; k += 2) {
                ulonglong2 pp0 = pb[k];
                acc0 = fma2_(E[2 * k],     pp0.x, acc0);
                acc1 = fma2_(E[2 * k + 1], pp0.y, acc1);
                ulonglong2 pp1 = pb[k + 1];
                acc2 = fma2_(E[2 * k + 2], pp1.x, acc2);
                acc3 = fma2_(E[2 * k + 3], pp1.y, acc3);
            }
            unsigned long long acc = add2_(add2_(acc0, acc1), add2_(acc2, acc3));
            float S_lo, S_hi;
            unpack_(acc, S_lo, S_hi);

            // new alpha = m + feat + log(S); floor avoids log(0) on START row
            const float n_lo = fmaf(lg2f_(fmaxf(S_lo, 1e-37f)), LN2, m + fc_lo);
            const float n_hi = fmaf(lg2f_(fmaxf(S_hi, 1e-37f)), LN2, m + fc_hi);

            // masked blend (mask is exactly 0.0 or 1.0)
            a_lo = fmaf(mc, n_lo - a_lo, a_lo);
            a_hi = fmaf(mc, n_hi - a_hi, a_hi);
        }
    }

    // out[b] = LSE_j( alpha[j] + T[END][j] )
    const float x_lo = a_lo + t_lo;
    const float x_hi = a_hi + t_hi;
    float m = fmaxf(x_lo, x_hi);
#pragma unroll
    for (int d = 16; d; d >>= 1)
        m = fmaxf(m, __shfl_xor_sync(0xffffffffu, m, d));
    const float c = -m * L2E;
    float ssum = ex2f_(fmaf(x_lo, L2E, c)) + ex2f_(fmaf(x_hi, L2E, c));
#pragma unroll
    for (int d = 16; d; d >>= 1)
        ssum += __shfl_xor_sync(0xffffffffu, ssum, d);
    if (lane == 0) out[b] = fmaf(lg2f_(ssum), LN2, m);
}

extern "C" void kernel_launch(void* const* d_in, const int* in_sizes, int n_in,
                              void* d_out, int out_size) {
    // identify inputs by element count (robust to ordering)
    const float* feats = nullptr;
    const float* maskp = nullptr;
    const float* trans = nullptr;
    for (int i = 0; i < n_in; ++i) {
        if (in_sizes[i] == SEQ * BATCH * NTAG)      feats = (const float*)d_in[i];
        else if (in_sizes[i] == SEQ * BATCH)        maskp = (const float*)d_in[i];
        else if (in_sizes[i] == NTAG * NTAG)        trans = (const float*)d_in[i];
    }
    crf_setup<<<8, 256>>>(trans);
    crf_main<<<BATCH / 8, 256>>>(feats, maskp, trans, (float*)d_out);
}